// round 3
// baseline (speedup 1.0000x reference)
#include <cuda_runtime.h>

// ArcFace loss, single fused kernel:
//   tgt[i]   = wf[i, labels[i]]
//   num[i]   = S*(t*cosM - sqrt(1-t^2)*sinM)     (== S*cos(acos(clip t)+M))
//   excl[i]  = sum_j exp(S*wf[i,j]) - exp(S*tgt[i])
//   L[i]     = num[i] - log(exp(num[i]) + excl[i])
//   out      = -mean(L)
//
// wf: [B=8192, C=10000] fp32 (327.7 MB, HBM-bound single pass ~48us achievable)
// labels: [B] int32 (harness downcasts int64 indices)
//
// The final mean is folded in via a last-block pattern: after writing L[row],
// each block bumps a device counter; the last block to arrive sums g_L in a
// fixed order (deterministic) and writes the scalar output. The counter is
// reset by that same block, so graph replays start clean.

#define MAX_B 16384

static __device__ float        g_L[MAX_B];
static __device__ unsigned int g_done_count = 0;

#define SCALE 64.0f
#define COS_M 0.8775825618903728f   // cos(0.5)
#define SIN_M 0.479425538604203f    // sin(0.5)
#define EPSC  1e-7f

__global__ __launch_bounds__(256) void arcface_fused_kernel(
    const float* __restrict__ wf,
    const int* __restrict__ labels,
    float* __restrict__ out,
    int C, int B)
{
    const int row = blockIdx.x;
    const float* __restrict__ p = wf + (size_t)row * (size_t)C;

    float acc = 0.0f;

    // Vectorized main path, unrolled x2 for MLP (C=10000 -> n4=2500)
    const int n4 = C >> 2;
    const float4* __restrict__ p4 = (const float4*)p;
    int i = threadIdx.x;
    for (; i + 256 < n4; i += 512) {
        float4 a = p4[i];
        float4 b = p4[i + 256];
        acc += __expf(SCALE * a.x) + __expf(SCALE * a.y)
             + __expf(SCALE * a.z) + __expf(SCALE * a.w);
        acc += __expf(SCALE * b.x) + __expf(SCALE * b.y)
             + __expf(SCALE * b.z) + __expf(SCALE * b.w);
    }
    for (; i < n4; i += 256) {
        float4 a = p4[i];
        acc += __expf(SCALE * a.x) + __expf(SCALE * a.y)
             + __expf(SCALE * a.z) + __expf(SCALE * a.w);
    }
    // Scalar tail (empty when C % 4 == 0)
    for (int j = (n4 << 2) + threadIdx.x; j < C; j += 256) {
        acc += __expf(SCALE * p[j]);
    }

    // Block reduction: warp shuffle then smem across 8 warps
    #pragma unroll
    for (int o = 16; o > 0; o >>= 1)
        acc += __shfl_down_sync(0xffffffffu, acc, o);

    __shared__ float warp_sums[8];
    __shared__ bool  s_is_last;
    const int lane = threadIdx.x & 31;
    const int wid  = threadIdx.x >> 5;
    if (lane == 0) warp_sums[wid] = acc;
    __syncthreads();

    if (threadIdx.x == 0) {
        float s = 0.0f;
        #pragma unroll
        for (int k = 0; k < 8; k++) s += warp_sums[k];

        int lbl = labels[row];
        lbl = max(0, min(lbl, C - 1));           // defensive clamp

        const float t = p[lbl];                  // target cosine (L2-hot)
        float tc  = fminf(fmaxf(t, -1.0f + EPSC), 1.0f - EPSC);
        float num = SCALE * (tc * COS_M - sqrtf(fmaxf(1.0f - tc * tc, 0.0f)) * SIN_M);
        float excl  = s - __expf(SCALE * t);
        float denom = __expf(num) + excl;
        g_L[row] = num - __logf(denom);

        // Publish L[row], then count this block as done.
        __threadfence();
        unsigned int prev = atomicAdd(&g_done_count, 1u);
        s_is_last = (prev == (unsigned int)(gridDim.x - 1));
    }
    __syncthreads();

    // Last block folds the mean. Fixed-order summation -> deterministic.
    if (s_is_last) {
        float racc = 0.0f;
        for (int r = threadIdx.x; r < B; r += 256)
            racc += g_L[r];

        #pragma unroll
        for (int o = 16; o > 0; o >>= 1)
            racc += __shfl_down_sync(0xffffffffu, racc, o);

        __shared__ float red_sums[8];
        if (lane == 0) red_sums[wid] = racc;
        __syncthreads();

        if (threadIdx.x == 0) {
            float total = 0.0f;
            #pragma unroll
            for (int k = 0; k < 8; k++) total += red_sums[k];
            out[0] = -total / (float)B;
            g_done_count = 0;                    // reset for next graph replay
        }
    }
}

extern "C" void kernel_launch(void* const* d_in, const int* in_sizes, int n_in,
                              void* d_out, int out_size)
{
    const float* wf     = (const float*)d_in[0];
    const int*   labels = (const int*)d_in[1];
    float*       out    = (float*)d_out;

    const int B = in_sizes[1];               // 8192
    const int C = in_sizes[0] / B;           // 10000

    arcface_fused_kernel<<<B, 256>>>(wf, labels, out, C, B);
}

// round 4
// speedup vs baseline: 1.0464x; 1.0464x over previous
#include <cuda_runtime.h>

// ArcFace loss, single fused kernel:
//   tgt[i]   = wf[i, labels[i]]
//   num[i]   = S*(t*cosM - sqrt(1-t^2)*sinM)     (== S*cos(acos(clip t)+M))
//   excl[i]  = sum_j exp(S*wf[i,j]) - exp(S*tgt[i])
//   L[i]     = num[i] - log(exp(num[i]) + excl[i])
//   out      = -mean(L)
//
// wf: [B=8192, C=10000] fp32 (327.7 MB, HBM-bound single pass)
// labels: [B] int32 (harness downcasts int64 indices)
//
// Fusion via last-block pattern WITHOUT per-block gpu-scope fences:
//  - L[row] published with st.global.cg (bypasses L1, visible at L2)
//  - done-counter bumped with atom.release.gpu (orders the st.cg, no L1 flush)
//  - only the last block issues one fence.acq_rel.gpu, then reads g_L via ldcg
// Counter reset by the last block -> clean state for every graph replay.

#define MAX_B 16384

static __device__ float        g_L[MAX_B];
static __device__ unsigned int g_done_count = 0;

#define SCALE 64.0f
#define COS_M 0.8775825618903728f   // cos(0.5)
#define SIN_M 0.479425538604203f    // sin(0.5)
#define EPSC  1e-7f

__global__ __launch_bounds__(256) void arcface_fused_kernel(
    const float* __restrict__ wf,
    const int* __restrict__ labels,
    float* __restrict__ out,
    int C, int B)
{
    const int row = blockIdx.x;
    const float* __restrict__ p = wf + (size_t)row * (size_t)C;

    float acc = 0.0f;

    // Simple strided float4 loop (round-2 proven form: ~82% of HBM spec).
    // C = 10000 -> n4 = 2500, C % 4 == 0 so scalar tail is empty.
    const int n4 = C >> 2;
    const float4* __restrict__ p4 = (const float4*)p;
    for (int i = threadIdx.x; i < n4; i += 256) {
        float4 v = p4[i];
        acc += __expf(SCALE * v.x);
        acc += __expf(SCALE * v.y);
        acc += __expf(SCALE * v.z);
        acc += __expf(SCALE * v.w);
    }
    for (int j = (n4 << 2) + threadIdx.x; j < C; j += 256) {
        acc += __expf(SCALE * p[j]);
    }

    // Block reduction: warp shuffle then smem across 8 warps
    #pragma unroll
    for (int o = 16; o > 0; o >>= 1)
        acc += __shfl_down_sync(0xffffffffu, acc, o);

    __shared__ float warp_sums[8];
    __shared__ bool  s_is_last;
    const int lane = threadIdx.x & 31;
    const int wid  = threadIdx.x >> 5;
    if (lane == 0) warp_sums[wid] = acc;
    __syncthreads();

    if (threadIdx.x == 0) {
        float s = 0.0f;
        #pragma unroll
        for (int k = 0; k < 8; k++) s += warp_sums[k];

        int lbl = labels[row];
        lbl = max(0, min(lbl, C - 1));           // defensive clamp

        const float t = p[lbl];                  // target cosine (L1/L2-hot)
        float tc  = fminf(fmaxf(t, -1.0f + EPSC), 1.0f - EPSC);
        float num = SCALE * (tc * COS_M - sqrtf(fmaxf(1.0f - tc * tc, 0.0f)) * SIN_M);
        float excl  = s - __expf(SCALE * t);
        float denom = __expf(num) + excl;
        float Lval  = num - __logf(denom);

        // Publish L[row] straight to L2 (no L1 involvement, no fence needed
        // on the write path beyond the release below).
        asm volatile("st.global.cg.f32 [%0], %1;"
                     :: "l"(&g_L[row]), "f"(Lval) : "memory");

        // Release-ordered done-count: orders the st.cg above without a
        // gpu-scope MEMBAR + CCTL.IVALL per block.
        unsigned int prev;
        asm volatile("atom.release.gpu.global.add.u32 %0, [%1], %2;"
                     : "=r"(prev)
                     : "l"(&g_done_count), "r"(1u)
                     : "memory");
        s_is_last = (prev == (unsigned int)(gridDim.x - 1));
    }
    __syncthreads();

    // Last block folds the mean. Fixed-order summation -> deterministic.
    if (s_is_last) {
        if (threadIdx.x == 0) {
            // Single acquire-side fence for the whole grid (one L1 flush total).
            asm volatile("fence.acq_rel.gpu;" ::: "memory");
        }
        __syncthreads();

        float racc = 0.0f;
        for (int r = threadIdx.x; r < B; r += 256)
            racc += __ldcg(&g_L[r]);             // L2 reads, bypass L1

        #pragma unroll
        for (int o = 16; o > 0; o >>= 1)
            racc += __shfl_down_sync(0xffffffffu, racc, o);

        __shared__ float red_sums[8];
        if (lane == 0) red_sums[wid] = racc;
        __syncthreads();

        if (threadIdx.x == 0) {
            float total = 0.0f;
            #pragma unroll
            for (int k = 0; k < 8; k++) total += red_sums[k];
            out[0] = -total / (float)B;
            g_done_count = 0;                    // reset for next graph replay
        }
    }
}

extern "C" void kernel_launch(void* const* d_in, const int* in_sizes, int n_in,
                              void* d_out, int out_size)
{
    const float* wf     = (const float*)d_in[0];
    const int*   labels = (const int*)d_in[1];
    float*       out    = (float*)d_out;

    const int B = in_sizes[1];               // 8192
    const int C = in_sizes[0] / B;           // 10000

    arcface_fused_kernel<<<B, 256>>>(wf, labels, out, C, B);
}

// round 5
// speedup vs baseline: 1.1401x; 1.0896x over previous
#include <cuda_runtime.h>

// ArcFace loss, two-kernel structure (fusion measured SLOWER in R3/R4):
//   tgt[i]   = wf[i, labels[i]]
//   num[i]   = S*(t*cosM - sqrt(1-t^2)*sinM)     (== S*cos(acos(clip t)+M))
//   excl[i]  = sum_j exp(S*wf[i,j]) - exp(S*tgt[i])
//   L[i]     = num[i] - log(exp(num[i]) + excl[i])
//   out      = -mean(L)
//
// wf: [B=8192, C=10000] fp32 (327.7 MB, HBM-bound single pass; R2 measured
//     ~50.4us = 6.5 TB/s on this exact row kernel)
// labels: [B] int32 (harness downcasts int64 indices)

#define MAX_B 16384

static __device__ float g_L[MAX_B];

#define SCALE 64.0f
#define COS_M 0.8775825618903728f   // cos(0.5)
#define SIN_M 0.479425538604203f    // sin(0.5)
#define EPSC  1e-7f

// ---------- Row kernel: EXACT round-2 form (proven fastest streaming) ----------
__global__ __launch_bounds__(256) void arcface_row_kernel(
    const float* __restrict__ wf,
    const int* __restrict__ labels,
    int C)
{
    const int row = blockIdx.x;
    const float* __restrict__ p = wf + (size_t)row * (size_t)C;

    float acc = 0.0f;

    // Vectorized main path (C % 4 == 0: 10000 = 2500 * 4)
    const int n4 = C >> 2;
    const float4* __restrict__ p4 = (const float4*)p;
    for (int i = threadIdx.x; i < n4; i += 256) {
        float4 v = p4[i];
        acc += __expf(SCALE * v.x);
        acc += __expf(SCALE * v.y);
        acc += __expf(SCALE * v.z);
        acc += __expf(SCALE * v.w);
    }
    // Scalar tail (empty when C % 4 == 0)
    for (int i = (n4 << 2) + threadIdx.x; i < C; i += 256) {
        acc += __expf(SCALE * p[i]);
    }

    // Block reduction: warp shuffle then smem across 8 warps
    #pragma unroll
    for (int o = 16; o > 0; o >>= 1)
        acc += __shfl_down_sync(0xffffffffu, acc, o);

    __shared__ float warp_sums[8];
    const int lane = threadIdx.x & 31;
    const int wid  = threadIdx.x >> 5;
    if (lane == 0) warp_sums[wid] = acc;
    __syncthreads();

    if (threadIdx.x == 0) {
        float s = 0.0f;
        #pragma unroll
        for (int i = 0; i < 8; i++) s += warp_sums[i];

        int lbl = labels[row];
        lbl = max(0, min(lbl, C - 1));           // defensive clamp

        const float t = p[lbl];                  // target cosine (L2-hot)
        float tc = fminf(fmaxf(t, -1.0f + EPSC), 1.0f - EPSC);
        float num = SCALE * (tc * COS_M - sqrtf(fmaxf(1.0f - tc * tc, 0.0f)) * SIN_M);
        float excl = s - __expf(SCALE * t);
        float denom = __expf(num) + excl;
        g_L[row] = num - __logf(denom);
    }
}

// ---------- Reduce kernel: lightweight (was 5.5us with 1024-thread smem tree) ----------
__global__ __launch_bounds__(256) void arcface_reduce_kernel(float* __restrict__ out, int B)
{
    // B = 8192 floats, L2-hot from the row kernel. 256 threads, float4 loads.
    const int n4 = B >> 2;
    const float4* __restrict__ p4 = (const float4*)g_L;

    float acc = 0.0f;
    for (int i = threadIdx.x; i < n4; i += 256) {
        float4 v = p4[i];
        acc += v.x + v.y + v.z + v.w;
    }
    // Tail for B not divisible by 4 (empty for B=8192)
    for (int i = (n4 << 2) + threadIdx.x; i < B; i += 256)
        acc += g_L[i];

    #pragma unroll
    for (int o = 16; o > 0; o >>= 1)
        acc += __shfl_down_sync(0xffffffffu, acc, o);

    __shared__ float warp_sums[8];
    const int lane = threadIdx.x & 31;
    const int wid  = threadIdx.x >> 5;
    if (lane == 0) warp_sums[wid] = acc;
    __syncthreads();

    if (threadIdx.x == 0) {
        float total = 0.0f;
        #pragma unroll
        for (int i = 0; i < 8; i++) total += warp_sums[i];
        out[0] = -total / (float)B;
    }
}

extern "C" void kernel_launch(void* const* d_in, const int* in_sizes, int n_in,
                              void* d_out, int out_size)
{
    const float* wf     = (const float*)d_in[0];
    const int*   labels = (const int*)d_in[1];
    float*       out    = (float*)d_out;

    const int B = in_sizes[1];               // 8192
    const int C = in_sizes[0] / B;           // 10000

    arcface_row_kernel<<<B, 256>>>(wf, labels, C);
    arcface_reduce_kernel<<<1, 256>>>(out, B);
}

// round 7
// speedup vs baseline: 1.1731x; 1.0289x over previous
#include <cuda_runtime.h>

// ArcFace loss, two-kernel structure with PDL overlap (+ safe fallback):
//   tgt[i]   = wf[i, labels[i]]
//   num[i]   = S*(t*cosM - sqrt(1-t^2)*sinM)     (== S*cos(acos(clip t)+M))
//   excl[i]  = sum_j exp(S*wf[i,j]) - exp(S*tgt[i])
//   L[i]     = num[i] - log(exp(num[i]) + excl[i])
//   out      = -mean(L)
//
// wf: [B=8192, C=10000] fp32 (327.7 MB, HBM-bound single pass)
// labels: [B] int32 (harness downcasts int64 indices)
//
// R5 evidence: the reduce kernel costs ~5.5us regardless of body size ->
// fixed launch/ramp overhead. Hide it with programmatic dependent launch:
// the reduce launches early (grid setup overlaps the row kernel's tail) and
// blocks on cudaGridDependencySynchronize() until the row grid completes
// (implicit completion trigger => full memory visibility, no fences needed).
// If the PDL-attributed launch is rejected at capture time, fall back to a
// plain launch of a non-PDL reduce kernel.

#define MAX_B 16384

static __device__ float g_L[MAX_B];

#define SCALE 64.0f
#define COS_M 0.8775825618903728f   // cos(0.5)
#define SIN_M 0.479425538604203f    // sin(0.5)
#define EPSC  1e-7f

// ---------- Row kernel: R2 proven form + streaming loads ----------
__global__ __launch_bounds__(256) void arcface_row_kernel(
    const float* __restrict__ wf,
    const int* __restrict__ labels,
    int C)
{
    const int row = blockIdx.x;
    const float* __restrict__ p = wf + (size_t)row * (size_t)C;

    float acc = 0.0f;

    // Vectorized main path (C % 4 == 0: 10000 = 2500 * 4).
    // __ldcs: read-once stream, evict-first (don't churn L2 with 327 MB).
    const int n4 = C >> 2;
    const float4* __restrict__ p4 = (const float4*)p;
    for (int i = threadIdx.x; i < n4; i += 256) {
        float4 v = __ldcs(&p4[i]);
        acc += __expf(SCALE * v.x);
        acc += __expf(SCALE * v.y);
        acc += __expf(SCALE * v.z);
        acc += __expf(SCALE * v.w);
    }
    // Scalar tail (empty when C % 4 == 0)
    for (int i = (n4 << 2) + threadIdx.x; i < C; i += 256) {
        acc += __expf(SCALE * p[i]);
    }

    // Block reduction: warp shuffle then smem across 8 warps
    #pragma unroll
    for (int o = 16; o > 0; o >>= 1)
        acc += __shfl_down_sync(0xffffffffu, acc, o);

    __shared__ float warp_sums[8];
    const int lane = threadIdx.x & 31;
    const int wid  = threadIdx.x >> 5;
    if (lane == 0) warp_sums[wid] = acc;
    __syncthreads();

    if (threadIdx.x == 0) {
        float s = 0.0f;
        #pragma unroll
        for (int i = 0; i < 8; i++) s += warp_sums[i];

        int lbl = labels[row];
        lbl = max(0, min(lbl, C - 1));           // defensive clamp

        const float t = p[lbl];                  // target cosine
        float tc = fminf(fmaxf(t, -1.0f + EPSC), 1.0f - EPSC);
        float num = SCALE * (tc * COS_M - sqrtf(fmaxf(1.0f - tc * tc, 0.0f)) * SIN_M);
        float excl = s - __expf(SCALE * t);
        float denom = __expf(num) + excl;
        g_L[row] = num - __logf(denom);
    }
}

// ---------- Shared reduce body ----------
__device__ __forceinline__ void reduce_body(float* __restrict__ out, int B)
{
    const int n4 = B >> 2;
    const float4* __restrict__ p4 = (const float4*)g_L;

    float acc = 0.0f;
    for (int i = threadIdx.x; i < n4; i += 256) {
        float4 v = p4[i];
        acc += v.x + v.y + v.z + v.w;
    }
    for (int i = (n4 << 2) + threadIdx.x; i < B; i += 256)
        acc += g_L[i];

    #pragma unroll
    for (int o = 16; o > 0; o >>= 1)
        acc += __shfl_down_sync(0xffffffffu, acc, o);

    __shared__ float warp_sums[8];
    const int lane = threadIdx.x & 31;
    const int wid  = threadIdx.x >> 5;
    if (lane == 0) warp_sums[wid] = acc;
    __syncthreads();

    if (threadIdx.x == 0) {
        float total = 0.0f;
        #pragma unroll
        for (int i = 0; i < 8; i++) total += warp_sums[i];
        out[0] = -total / (float)B;
    }
}

// PDL variant: waits on the prior grid via the dependency trigger.
__global__ __launch_bounds__(256) void arcface_reduce_pdl(float* __restrict__ out, int B)
{
    cudaGridDependencySynchronize();
    reduce_body(out, B);
}

// Plain variant: ordinary stream ordering provides the dependency.
__global__ __launch_bounds__(256) void arcface_reduce_plain(float* __restrict__ out, int B)
{
    reduce_body(out, B);
}

extern "C" void kernel_launch(void* const* d_in, const int* in_sizes, int n_in,
                              void* d_out, int out_size)
{
    const float* wf     = (const float*)d_in[0];
    const int*   labels = (const int*)d_in[1];
    float*       out    = (float*)d_out;

    const int B = in_sizes[1];               // 8192
    const int C = in_sizes[0] / B;           // 10000

    arcface_row_kernel<<<B, 256>>>(wf, labels, C);

    // Try a PDL-attributed secondary launch: it may begin (grid setup +
    // preamble) while the row kernel is still running; ordering comes from
    // cudaGridDependencySynchronize() inside. Fall back to a plain launch
    // if the attributed launch is rejected (e.g. unsupported under capture).
    cudaLaunchAttribute attr[1];
    attr[0].id = cudaLaunchAttributeProgrammaticStreamSerialization;
    attr[0].val.programmaticStreamSerializationAllowed = 1;

    cudaLaunchConfig_t cfg = {};
    cfg.gridDim  = dim3(1, 1, 1);
    cfg.blockDim = dim3(256, 1, 1);
    cfg.dynamicSmemBytes = 0;
    cfg.stream   = 0;                        // legacy default stream (captured)
    cfg.attrs    = attr;
    cfg.numAttrs = 1;

    cudaError_t e = cudaLaunchKernelEx(&cfg, arcface_reduce_pdl, out, B);
    if (e != cudaSuccess) {
        (void)cudaGetLastError();            // clear sticky error
        arcface_reduce_plain<<<1, 256>>>(out, B);
    }
}